// round 12
// baseline (speedup 1.0000x reference)
#include <cuda_runtime.h>

#define NMAX   131072
#define NNZMAX 3400000
#define BV     32

// Static scratch.
__device__ float g_xT[(size_t)NMAX * BV];     // x transposed (N, B)
__device__ int   g_count [NMAX];              // per-dst degree
__device__ int   g_rowptr[NMAX];              // exclusive prefix (start of row)
__device__ int   g_cursor[NMAX];              // fill cursor -> end of row
__device__ int   g_blocksum[1024];
__device__ int2  g_sorted[NNZMAX];            // dst-grouped (src, val_bits)

// ---------------------------------------------------------------------------
// Transpose x (B, N) -> g_xT (N, B). 4 tiles of 32x32 per CTA.
__global__ __launch_bounds__(1024) void transpose_x_kernel(
        const float* __restrict__ x, int N, int B) {
    __shared__ float tile[4][32][33];
    int n0 = blockIdx.x * 128;
    int tx = threadIdx.x, ty = threadIdx.y;
    #pragma unroll
    for (int t = 0; t < 4; t++) {
        int n = n0 + t * 32 + tx;
        if (ty < B && n < N) tile[t][ty][tx] = x[(size_t)ty * N + n];
    }
    __syncthreads();
    #pragma unroll
    for (int t = 0; t < 4; t++) {
        int nw = n0 + t * 32 + ty;
        if (tx < B && nw < N) g_xT[(size_t)nw * BV + tx] = tile[t][tx][ty];
    }
}

// Histogram of dst (spread over 100k counters -> low contention).
__global__ void hist_kernel(const int* __restrict__ idx, int nnz) {
    int i = blockIdx.x * blockDim.x + threadIdx.x;
    if (i < nnz) atomicAdd(&g_count[__ldg(idx + nnz + i)], 1);
}

// Exclusive scan, level 1 (1024-wide blocks).
__global__ void scan_block_kernel(int M) {
    __shared__ int sh[1024];
    int gid = blockIdx.x * 1024 + threadIdx.x;
    int v = (gid < M) ? g_count[gid] : 0;
    sh[threadIdx.x] = v;
    __syncthreads();
    for (int off = 1; off < 1024; off <<= 1) {
        int t = (threadIdx.x >= off) ? sh[threadIdx.x - off] : 0;
        __syncthreads();
        sh[threadIdx.x] += t;
        __syncthreads();
    }
    if (gid < M) g_rowptr[gid] = sh[threadIdx.x] - v;
    if (threadIdx.x == 1023) g_blocksum[blockIdx.x] = sh[1023];
}

// Exclusive scan, level 2 (block sums, nblk <= 1024).
__global__ void scan_top_kernel(int nblk) {
    __shared__ int sh[1024];
    int v = (threadIdx.x < nblk) ? g_blocksum[threadIdx.x] : 0;
    sh[threadIdx.x] = v;
    __syncthreads();
    for (int off = 1; off < 1024; off <<= 1) {
        int t = (threadIdx.x >= off) ? sh[threadIdx.x - off] : 0;
        __syncthreads();
        sh[threadIdx.x] += t;
        __syncthreads();
    }
    if (threadIdx.x < nblk) g_blocksum[threadIdx.x] = sh[threadIdx.x] - v;
}

// Add block offsets; init cursors.
__global__ void scan_add_kernel(int M) {
    int gid = blockIdx.x * 1024 + threadIdx.x;
    if (gid < M) {
        int o = g_rowptr[gid] + g_blocksum[blockIdx.x];
        g_rowptr[gid] = o;
        g_cursor[gid] = o;
    }
}

// Scatter edges into dst-grouped order (spread cursors, 8B records).
__global__ void scatter_kernel(const int* __restrict__ idx,
                               const float* __restrict__ vals, int nnz) {
    int i = blockIdx.x * blockDim.x + threadIdx.x;
    if (i >= nnz) return;
    int dst = __ldg(idx + nnz + i);
    int pos = atomicAdd(&g_cursor[dst], 1);
    g_sorted[pos] = make_int2(__ldg(idx + i), __float_as_int(__ldg(vals + i)));
}

// ---------------------------------------------------------------------------
// CSR gather: warp per dst row, lane = batch. Records broadcast-loaded,
// row gathers coalesced 128B, 4 independent accumulators, zero atomics.
// Output transpose + bias fused through a smem tile.
__global__ __launch_bounds__(1024, 2) void gather_kernel(
        float* __restrict__ out, const float* __restrict__ bias, int M, int B) {
    __shared__ float tile[32][33];
    int m0 = blockIdx.x * 32;
    int tx = threadIdx.x;                  // lane = batch
    int ty = threadIdx.y;                  // warp = row
    int m  = m0 + ty;

    float s0 = 0.f, s1 = 0.f, s2 = 0.f, s3 = 0.f;
    if (m < M) {
        int p = g_rowptr[m];
        int e = g_cursor[m];               // end of row after scatter
        #pragma unroll 1
        for (; p + 4 <= e; p += 4) {
            int2 r0 = __ldg(&g_sorted[p + 0]);   // uniform -> broadcast
            int2 r1 = __ldg(&g_sorted[p + 1]);
            int2 r2 = __ldg(&g_sorted[p + 2]);
            int2 r3 = __ldg(&g_sorted[p + 3]);
            float x0 = g_xT[(size_t)r0.x * BV + tx];
            float x1 = g_xT[(size_t)r1.x * BV + tx];
            float x2 = g_xT[(size_t)r2.x * BV + tx];
            float x3 = g_xT[(size_t)r3.x * BV + tx];
            s0 += __int_as_float(r0.y) * x0;
            s1 += __int_as_float(r1.y) * x1;
            s2 += __int_as_float(r2.y) * x2;
            s3 += __int_as_float(r3.y) * x3;
        }
        for (; p < e; p++) {
            int2 r = __ldg(&g_sorted[p]);
            s0 += __int_as_float(r.y) * g_xT[(size_t)r.x * BV + tx];
        }
    }
    tile[ty][tx] = (s0 + s1) + (s2 + s3);
    __syncthreads();
    int mo = m0 + tx;
    if (mo < M && ty < B)
        out[(size_t)ty * M + mo] = tile[tx][ty] + __ldg(bias + mo);
}

// ---------------------------------------------------------------------------
extern "C" void kernel_launch(void* const* d_in, const int* in_sizes, int n_in,
                              void* d_out, int out_size) {
    const float* x    = (const float*)d_in[0];   // (B, N, 1)
    const int*   idx  = (const int*)  d_in[1];   // (2, NNZ): row0=src, row1=dst
    const float* vals = (const float*)d_in[2];   // (NNZ,)
    const float* bias = (const float*)d_in[3];   // (M, 1)
    float*       out  = (float*)d_out;           // (B, M, 1)

    int M    = in_sizes[3];
    int NNZ  = in_sizes[1] / 2;
    int B    = out_size / M;
    int N    = in_sizes[0] / B;
    int nblk = (M + 1023) / 1024;

    // zero the histogram (capturable, not an allocation)
    void* countp = nullptr;
    cudaGetSymbolAddress(&countp, g_count);
    cudaMemsetAsync(countp, 0, (size_t)M * sizeof(int));

    {
        dim3 blk(32, 32);
        transpose_x_kernel<<<(N + 127) / 128, blk>>>(x, N, B);
    }

    hist_kernel<<<(NNZ + 511) / 512, 512>>>(idx, NNZ);

    scan_block_kernel<<<nblk, 1024>>>(M);
    scan_top_kernel<<<1, 1024>>>(nblk);
    scan_add_kernel<<<nblk, 1024>>>(M);

    scatter_kernel<<<(NNZ + 511) / 512, 512>>>(idx, vals, NNZ);

    {
        dim3 blk(32, 32);
        gather_kernel<<<(M + 31) / 32, blk>>>(out, bias, M, B);
    }
}

// round 13
// speedup vs baseline: 1.0512x; 1.0512x over previous
#include <cuda_runtime.h>

#define NMAX 131072
#define BV   32          // batch, inner stride of xT / acc

// Scratch: x transposed to (N, B) and accumulator (M, B).
// g_acc invariant: all-zero at kernel_launch entry (zero-init at load,
// restored by write_out_kernel at the end of every call).
__device__ float g_xT [(size_t)NMAX * BV];
__device__ float g_acc[(size_t)NMAX * BV];

// ---------------------------------------------------------------------------
// Transpose x (B, N) -> g_xT (N, B). 4 tiles of 32x32 per CTA for MLP.
__global__ __launch_bounds__(1024) void transpose_x_kernel(
        const float* __restrict__ x, int N, int B) {
    __shared__ float tile[4][32][33];
    int n0 = blockIdx.x * 128;
    int tx = threadIdx.x, ty = threadIdx.y;   // ty = batch on load
    #pragma unroll
    for (int t = 0; t < 4; t++) {
        int n = n0 + t * 32 + tx;
        if (ty < B && n < N)
            tile[t][ty][tx] = x[(size_t)ty * N + n];        // coalesced in n
    }
    __syncthreads();
    #pragma unroll
    for (int t = 0; t < 4; t++) {
        int nw = n0 + t * 32 + ty;
        if (tx < B && nw < N)
            g_xT[(size_t)nw * BV + tx] = tile[t][tx][ty];   // coalesced in b
    }
}

// ---------------------------------------------------------------------------
// Edge scatter: 4 threads per edge, two float4 groups (8 batches) per thread.
// Gather 2x16B of xT[src], FMA by edge weight, vectorized red to acc[dst].
__global__ __launch_bounds__(256) void edge_kernel(
        const int* __restrict__ idx, const float* __restrict__ vals, int nnz) {
    int tid = blockIdx.x * blockDim.x + threadIdx.x;
    int e = tid >> 2;          // edge id (8 edges per warp)
    int g = tid & 3;           // pair of batch groups
    if (e >= nnz) return;

    int   src = __ldg(idx + e);
    int   dst = __ldg(idx + nnz + e);
    float v   = __ldg(vals + e);

    const float4* xp = reinterpret_cast<const float4*>(g_xT + (size_t)src * BV) + g * 2;
    float4 xa = __ldg(xp);
    float4 xb = __ldg(xp + 1);

    float* ap = g_acc + (size_t)dst * BV + g * 8;
    asm volatile("red.global.add.v4.f32 [%0], {%1, %2, %3, %4};"
                 :: "l"(ap), "f"(xa.x * v), "f"(xa.y * v),
                    "f"(xa.z * v), "f"(xa.w * v)
                 : "memory");
    asm volatile("red.global.add.v4.f32 [%0], {%1, %2, %3, %4};"
                 :: "l"(ap + 4), "f"(xb.x * v), "f"(xb.y * v),
                    "f"(xb.z * v), "f"(xb.w * v)
                 : "memory");
}

// ---------------------------------------------------------------------------
// Transpose acc (M, B) -> out (B, M) + bias, 4 tiles of 32x32 per CTA, and
// restore the acc==0 invariant for the next graph replay.
__global__ __launch_bounds__(1024) void write_out_kernel(
        float* __restrict__ out, const float* __restrict__ bias, int M, int B) {
    __shared__ float tile[4][32][33];
    int m0 = blockIdx.x * 128;
    int tx = threadIdx.x, ty = threadIdx.y;
    #pragma unroll
    for (int t = 0; t < 4; t++) {
        int m = m0 + t * 32 + ty;
        if (m < M && tx < B) {
            size_t a = (size_t)m * BV + tx;
            tile[t][ty][tx] = g_acc[a];                     // coalesced in b
            g_acc[a] = 0.f;                                 // re-zero for next call
        }
    }
    __syncthreads();
    #pragma unroll
    for (int t = 0; t < 4; t++) {
        int mo = m0 + t * 32 + tx;
        if (mo < M && ty < B)
            out[(size_t)ty * M + mo] = tile[t][tx][ty] + __ldg(bias + mo);
    }
}

// ---------------------------------------------------------------------------
extern "C" void kernel_launch(void* const* d_in, const int* in_sizes, int n_in,
                              void* d_out, int out_size) {
    const float* x    = (const float*)d_in[0];   // (B, N, 1)
    const int*   idx  = (const int*)  d_in[1];   // (2, NNZ): row0=src, row1=dst
    const float* vals = (const float*)d_in[2];   // (NNZ,)
    const float* bias = (const float*)d_in[3];   // (M, 1)
    float*       out  = (float*)d_out;           // (B, M, 1)

    int M   = in_sizes[3];
    int NNZ = in_sizes[1] / 2;
    int B   = out_size / M;
    int N   = in_sizes[0] / B;

    {   // 1) transpose x -> xT (N, B)
        dim3 blk(32, 32);
        transpose_x_kernel<<<(N + 127) / 128, blk>>>(x, N, B);
    }
    {   // 2) edge scatter with vectorized global reductions (acc starts at 0)
        long long threads = (long long)NNZ * 4;
        int blocks = (int)((threads + 255) / 256);
        edge_kernel<<<blocks, 256>>>(idx, vals, NNZ);
    }
    {   // 3) transpose acc -> out, add bias, re-zero acc
        dim3 blk(32, 32);
        write_out_kernel<<<(M + 127) / 128, blk>>>(out, bias, M, B);
    }
}

// round 15
// speedup vs baseline: 1.2235x; 1.1639x over previous
#include <cuda_runtime.h>

#define NMAX 131072
#define BV   32          // batch, inner stride of xT / acc

// Scratch: x transposed to (N, B) and accumulator (M, B).
// g_acc invariant: all-zero at kernel_launch entry (zero-init at load,
// restored by write_out_kernel at the end of every call).
__device__ float g_xT [(size_t)NMAX * BV];
__device__ float g_acc[(size_t)NMAX * BV];

// ---------------------------------------------------------------------------
// Transpose x (B, N) -> g_xT (N, B). 4 tiles of 32x32 per CTA for MLP.
__global__ __launch_bounds__(1024) void transpose_x_kernel(
        const float* __restrict__ x, int N, int B) {
    __shared__ float tile[4][32][33];
    int n0 = blockIdx.x * 128;
    int tx = threadIdx.x, ty = threadIdx.y;   // ty = batch on load
    #pragma unroll
    for (int t = 0; t < 4; t++) {
        int n = n0 + t * 32 + tx;
        if (ty < B && n < N)
            tile[t][ty][tx] = x[(size_t)ty * N + n];        // coalesced in n
    }
    __syncthreads();
    #pragma unroll
    for (int t = 0; t < 4; t++) {
        int nw = n0 + t * 32 + ty;
        if (tx < B && nw < N)
            g_xT[(size_t)nw * BV + tx] = tile[t][tx][ty];   // coalesced in b
    }
}

// ---------------------------------------------------------------------------
// Edge scatter (R8-proven shape): 8 threads per edge, one float4 (4 batches)
// per thread. Gather 16B of xT[src], FMA by weight, vectorized red to acc[dst].
__global__ void edge_kernel(const int* __restrict__ idx,
                            const float* __restrict__ vals, int nnz) {
    int tid = blockIdx.x * blockDim.x + threadIdx.x;
    int e = tid >> 3;          // edge id
    int g = tid & 7;           // batch group (4 floats)
    if (e >= nnz) return;

    int   src = __ldg(idx + e);
    int   dst = __ldg(idx + nnz + e);
    float v   = __ldg(vals + e);

    const float4* xp = reinterpret_cast<const float4*>(g_xT + (size_t)src * BV) + g;
    float4 xv = __ldg(xp);

    float* ap = g_acc + (size_t)dst * BV + g * 4;
    asm volatile("red.global.add.v4.f32 [%0], {%1, %2, %3, %4};"
                 :: "l"(ap), "f"(xv.x * v), "f"(xv.y * v),
                    "f"(xv.z * v), "f"(xv.w * v)
                 : "memory");
}

// ---------------------------------------------------------------------------
// Transpose acc (M, B) -> out (B, M) + bias, 4 tiles of 32x32 per CTA, and
// restore the acc==0 invariant for the next graph replay.
__global__ __launch_bounds__(1024) void write_out_kernel(
        float* __restrict__ out, const float* __restrict__ bias, int M, int B) {
    __shared__ float tile[4][32][33];
    int m0 = blockIdx.x * 128;
    int tx = threadIdx.x, ty = threadIdx.y;
    #pragma unroll
    for (int t = 0; t < 4; t++) {
        int m = m0 + t * 32 + ty;
        if (m < M && tx < B) {
            size_t a = (size_t)m * BV + tx;
            tile[t][ty][tx] = g_acc[a];                     // coalesced in b
            g_acc[a] = 0.f;                                 // re-zero for next call
        }
    }
    __syncthreads();
    #pragma unroll
    for (int t = 0; t < 4; t++) {
        int mo = m0 + t * 32 + tx;
        if (mo < M && ty < B)
            out[(size_t)ty * M + mo] = tile[t][tx][ty] + __ldg(bias + mo);
    }
}

// ---------------------------------------------------------------------------
extern "C" void kernel_launch(void* const* d_in, const int* in_sizes, int n_in,
                              void* d_out, int out_size) {
    const float* x    = (const float*)d_in[0];   // (B, N, 1)
    const int*   idx  = (const int*)  d_in[1];   // (2, NNZ): row0=src, row1=dst
    const float* vals = (const float*)d_in[2];   // (NNZ,)
    const float* bias = (const float*)d_in[3];   // (M, 1)
    float*       out  = (float*)d_out;           // (B, M, 1)

    int M   = in_sizes[3];
    int NNZ = in_sizes[1] / 2;
    int B   = out_size / M;
    int N   = in_sizes[0] / B;

    {   // 1) transpose x -> xT (N, B)
        dim3 blk(32, 32);
        transpose_x_kernel<<<(N + 127) / 128, blk>>>(x, N, B);
    }
    {   // 2) edge scatter with vectorized global reductions (acc starts at 0)
        long long threads = (long long)NNZ * 8;
        int blocks = (int)((threads + 255) / 256);
        edge_kernel<<<blocks, 256>>>(idx, vals, NNZ);
    }
    {   // 3) transpose acc -> out, add bias, re-zero acc
        dim3 blk(32, 32);
        write_out_kernel<<<(M + 127) / 128, blk>>>(out, bias, M, B);
    }
}